// round 7
// baseline (speedup 1.0000x reference)
#include <cuda_runtime.h>
#include <cstdint>

#define N_NODES 50000
#define N_EDGES 640000
#define IN_CH   128
#define HID_CH  256
#define K_TOT   256
#define TILE_M  128
#define TILE_N  128
#define N_TILES 391             // ceil(50000/128)
#define CHUNK_K 16
#define N_CHUNKS 16
#define STAGES  4
#define PITCH   20              // floats per smem row: 16B-aligned, conflict-free

// Scratch (__device__ globals zero-initialized; pad rows of g_A never written).
__device__ int   g_cnt[N_NODES];                   // in-degree histogram
__device__ int   g_off[N_NODES];                   // CSR offsets
__device__ int   g_cur[N_NODES];                   // permute cursors
__device__ int   g_esrc[N_EDGES];                  // src ids grouped by dst
__device__ float g_Bt[HID_CH * K_TOT];             // Bt[n][k], tf32-rounded
__device__ float g_A[(N_TILES * TILE_M) * K_TOT];  // [mean | x], tf32-rounded

__device__ __forceinline__ uint32_t f2tf(float f) {
    uint32_t r;
    asm("cvt.rna.tf32.f32 %0, %1;" : "=r"(r) : "f"(f));
    return r;
}
__device__ __forceinline__ uint32_t smem_u32(const void* p) {
    return (uint32_t)__cvta_generic_to_shared(p);
}
__device__ __forceinline__ void cp16(uint32_t dst, const void* src) {
    asm volatile("cp.async.ca.shared.global [%0], [%1], 16;"
                 :: "r"(dst), "l"(src) : "memory");
}

// ---------------------------------------------------------------------------
// Kernel 1: zero the histogram.
// ---------------------------------------------------------------------------
__global__ void zero_cnt_kernel() {
    int i = blockIdx.x * blockDim.x + threadIdx.x;
    if (i < N_NODES) g_cnt[i] = 0;
}

// ---------------------------------------------------------------------------
// Kernel 2: in-degree histogram.
// ---------------------------------------------------------------------------
__global__ void hist_kernel(const int* __restrict__ edge_index) {
    int e = blockIdx.x * blockDim.x + threadIdx.x;
    if (e < N_EDGES) atomicAdd(&g_cnt[edge_index[N_EDGES + e]], 1);
}

// ---------------------------------------------------------------------------
// Kernel 3: exclusive prefix sum over g_cnt (1 block, 1024 threads, 2-level).
// ---------------------------------------------------------------------------
#define SCAN_PER 49   // 1024*49 = 50176 >= N_NODES
__global__ void __launch_bounds__(1024) scan_kernel() {
    __shared__ int part[1024];
    const int t = threadIdx.x;
    const int base = t * SCAN_PER;

    int local[SCAN_PER];
    int s = 0;
    #pragma unroll
    for (int i = 0; i < SCAN_PER; i++) {
        int idx = base + i;
        local[i] = (idx < N_NODES) ? g_cnt[idx] : 0;
        s += local[i];
    }
    part[t] = s;
    __syncthreads();
    #pragma unroll
    for (int d = 1; d < 1024; d <<= 1) {
        int v = (t >= d) ? part[t - d] : 0;
        __syncthreads();
        part[t] += v;
        __syncthreads();
    }
    int run = (t == 0) ? 0 : part[t - 1];
    #pragma unroll
    for (int i = 0; i < SCAN_PER; i++) {
        int idx = base + i;
        if (idx < N_NODES) {
            g_off[idx] = run;
            g_cur[idx] = run;
            run += local[i];
        }
    }
}

// ---------------------------------------------------------------------------
// Kernel 4: permute edge srcs into dst-grouped order.
// ---------------------------------------------------------------------------
__global__ void permute_kernel(const int* __restrict__ edge_index) {
    int e = blockIdx.x * blockDim.x + threadIdx.x;
    if (e < N_EDGES) {
        int dst = edge_index[N_EDGES + e];
        int pos = atomicAdd(&g_cur[dst], 1);
        g_esrc[pos] = edge_index[e];
    }
}

// ---------------------------------------------------------------------------
// Kernel 5: aggregate. One warp per node; lane = 4 channels (float4).
// Writes g_A[node] = [tf32(mean) | tf32(x)] directly (no g_agg, no prep).
// ---------------------------------------------------------------------------
__global__ void aggregate_kernel(const float* __restrict__ x) {
    int node = (blockIdx.x * blockDim.x + threadIdx.x) >> 5;
    int lane = threadIdx.x & 31;
    if (node >= N_NODES) return;

    const int off = g_off[node];
    const int cnt = g_cnt[node];

    float4 s0 = make_float4(0.f, 0.f, 0.f, 0.f);
    float4 s1 = make_float4(0.f, 0.f, 0.f, 0.f);
    int i = 0;
    for (; i + 2 <= cnt; i += 2) {
        int sa = g_esrc[off + i];         // broadcast across warp
        int sb = g_esrc[off + i + 1];
        float4 va = reinterpret_cast<const float4*>(x + (size_t)sa * IN_CH)[lane];
        float4 vb = reinterpret_cast<const float4*>(x + (size_t)sb * IN_CH)[lane];
        s0.x += va.x; s0.y += va.y; s0.z += va.z; s0.w += va.w;
        s1.x += vb.x; s1.y += vb.y; s1.z += vb.z; s1.w += vb.w;
    }
    if (i < cnt) {
        int sa = g_esrc[off + i];
        float4 va = reinterpret_cast<const float4*>(x + (size_t)sa * IN_CH)[lane];
        s0.x += va.x; s0.y += va.y; s0.z += va.z; s0.w += va.w;
    }
    s0.x += s1.x; s0.y += s1.y; s0.z += s1.z; s0.w += s1.w;

    float inv = 1.0f / fmaxf((float)cnt, 1.0f);
    float4 m;
    m.x = __uint_as_float(f2tf(s0.x * inv));
    m.y = __uint_as_float(f2tf(s0.y * inv));
    m.z = __uint_as_float(f2tf(s0.z * inv));
    m.w = __uint_as_float(f2tf(s0.w * inv));
    float4* arow = reinterpret_cast<float4*>(g_A + (size_t)node * K_TOT);
    arow[lane] = m;

    float4 xv = reinterpret_cast<const float4*>(x + (size_t)node * IN_CH)[lane];
    xv.x = __uint_as_float(f2tf(xv.x));
    xv.y = __uint_as_float(f2tf(xv.y));
    xv.z = __uint_as_float(f2tf(xv.z));
    xv.w = __uint_as_float(f2tf(xv.w));
    arow[32 + lane] = xv;
}

// ---------------------------------------------------------------------------
// Kernel 6: transpose W into K-major Bt[n][k], tf32-rounded.
// ---------------------------------------------------------------------------
__global__ void transpose_kernel(const float* __restrict__ W_l,
                                 const float* __restrict__ W_r) {
    int k = blockIdx.x;
    int n = threadIdx.x;
    float v = (k < IN_CH) ? W_l[k * HID_CH + n] : W_r[(k - IN_CH) * HID_CH + n];
    g_Bt[n * K_TOT + k] = __uint_as_float(f2tf(v));
}

// ---------------------------------------------------------------------------
// Kernel 7: tf32 mma.sync GEMM, cp.async 4-stage pipeline (unchanged from R6).
// ---------------------------------------------------------------------------
#define STAGE_BYTES (TILE_M * PITCH * 4)              // 10240
#define OFF_BIAS 0
#define OFF_A    512
#define OFF_B    (OFF_A + STAGES * STAGE_BYTES)       // 41472
#define SMEM_BYTES (OFF_B + STAGES * STAGE_BYTES)     // 82432

__device__ __forceinline__ void mma_tf32(float* c, const uint32_t* a,
                                         uint32_t b0, uint32_t b1) {
    asm("mma.sync.aligned.m16n8k8.row.col.f32.tf32.tf32.f32 "
        "{%0,%1,%2,%3}, {%4,%5,%6,%7}, {%8,%9}, {%0,%1,%2,%3};"
        : "+f"(c[0]), "+f"(c[1]), "+f"(c[2]), "+f"(c[3])
        : "r"(a[0]), "r"(a[1]), "r"(a[2]), "r"(a[3]), "r"(b0), "r"(b1));
}

__global__ void __launch_bounds__(256, 2)
gemm_kernel(const float* __restrict__ b_l, float* __restrict__ out) {
    extern __shared__ char smem[];
    const int tid = threadIdx.x;
    const int wid = tid >> 5, lid = tid & 31;
    const int lrow = lid >> 2, lane4 = lid & 3;
    const int node0 = blockIdx.x * TILE_M;
    const int nblk0 = blockIdx.y * TILE_N;
    const int m_base = (wid & 3) * 32;
    const int n_base = (wid >> 2) * 64;

    float* bias_s = (float*)(smem + OFF_BIAS);
    if (tid < TILE_N) bias_s[tid] = b_l[nblk0 + tid];

    const uint32_t sA = smem_u32(smem + OFF_A);
    const uint32_t sB = smem_u32(smem + OFF_B);

    const int r0 = tid >> 2, s0 = (tid & 3) * 4;
    const int r1 = (tid + 256) >> 2, s1 = s0;
    const float* gA0 = g_A + (size_t)(node0 + r0) * K_TOT + s0;
    const float* gA1 = g_A + (size_t)(node0 + r1) * K_TOT + s1;
    const float* gB0 = g_Bt + (size_t)(nblk0 + r0) * K_TOT + s0;
    const float* gB1 = g_Bt + (size_t)(nblk0 + r1) * K_TOT + s1;
    const uint32_t dA0 = (r0 * PITCH + s0) * 4, dA1 = (r1 * PITCH + s1) * 4;

    auto issue = [&](int c) {
        const int kc = c * CHUNK_K;
        const uint32_t bo = (uint32_t)(c & (STAGES - 1)) * STAGE_BYTES;
        cp16(sA + bo + dA0, gA0 + kc);
        cp16(sA + bo + dA1, gA1 + kc);
        cp16(sB + bo + dA0, gB0 + kc);
        cp16(sB + bo + dA1, gB1 + kc);
    };

    float acc[2][8][4];
    #pragma unroll
    for (int mi = 0; mi < 2; ++mi)
        #pragma unroll
        for (int ni = 0; ni < 8; ++ni)
            #pragma unroll
            for (int j = 0; j < 4; ++j) acc[mi][ni][j] = 0.f;

    issue(0); asm volatile("cp.async.commit_group;" ::: "memory");
    issue(1); asm volatile("cp.async.commit_group;" ::: "memory");
    issue(2); asm volatile("cp.async.commit_group;" ::: "memory");

    for (int c = 0; c < N_CHUNKS; ++c) {
        asm volatile("cp.async.wait_group 2;" ::: "memory");
        __syncthreads();

        if (c + 3 < N_CHUNKS) issue(c + 3);
        asm volatile("cp.async.commit_group;" ::: "memory");

        const float* As = (const float*)(smem + OFF_A + (c & (STAGES - 1)) * STAGE_BYTES);
        const float* Bs = (const float*)(smem + OFF_B + (c & (STAGES - 1)) * STAGE_BYTES);
        #pragma unroll
        for (int ks = 0; ks < 2; ++ks) {
            const int k0 = ks * 8;
            uint32_t a[2][4];
            #pragma unroll
            for (int mi = 0; mi < 2; ++mi) {
                const float* ap = As + (m_base + mi * 16 + lrow) * PITCH + k0 + lane4;
                a[mi][0] = __float_as_uint(ap[0]);
                a[mi][1] = __float_as_uint(ap[8 * PITCH]);
                a[mi][2] = __float_as_uint(ap[4]);
                a[mi][3] = __float_as_uint(ap[8 * PITCH + 4]);
            }
            #pragma unroll
            for (int ni = 0; ni < 8; ++ni) {
                const float* bp = Bs + (n_base + ni * 8 + lrow) * PITCH + k0 + lane4;
                uint32_t b0 = __float_as_uint(bp[0]);
                uint32_t b1 = __float_as_uint(bp[4]);
                mma_tf32(acc[0][ni], a[0], b0, b1);
                mma_tf32(acc[1][ni], a[1], b0, b1);
            }
        }
        __syncthreads();
    }

    #pragma unroll
    for (int mi = 0; mi < 2; ++mi) {
        int row = node0 + m_base + mi * 16 + lrow;
        #pragma unroll
        for (int ni = 0; ni < 8; ++ni) {
            int col = n_base + ni * 8 + lane4 * 2;
            float b0 = bias_s[col], b1 = bias_s[col + 1];
            if (row < N_NODES) {
                *reinterpret_cast<float2*>(out + (size_t)row * HID_CH + nblk0 + col) =
                    make_float2(acc[mi][ni][0] + b0, acc[mi][ni][1] + b1);
            }
            if (row + 8 < N_NODES) {
                *reinterpret_cast<float2*>(out + (size_t)(row + 8) * HID_CH + nblk0 + col) =
                    make_float2(acc[mi][ni][2] + b0, acc[mi][ni][3] + b1);
            }
        }
    }
}

// ---------------------------------------------------------------------------
// Launch. Inputs: x f32[50000*128], edge_index i32[2*640000],
// W_l f32[128*256], b_l f32[256], W_r f32[128*256]. Out f32[50000*256].
// ---------------------------------------------------------------------------
extern "C" void kernel_launch(void* const* d_in, const int* in_sizes, int n_in,
                              void* d_out, int out_size) {
    const float* x = (const float*)d_in[0];
    const int* edge_index = (const int*)d_in[1];
    const float* W_l = (const float*)d_in[2];
    const float* b_l = (const float*)d_in[3];
    const float* W_r = (const float*)d_in[4];
    float* out = (float*)d_out;

    cudaFuncSetAttribute(gemm_kernel,
                         cudaFuncAttributeMaxDynamicSharedMemorySize, SMEM_BYTES);

    zero_cnt_kernel<<<(N_NODES + 255) / 256, 256>>>();
    hist_kernel<<<(N_EDGES + 255) / 256, 256>>>(edge_index);
    scan_kernel<<<1, 1024>>>();
    permute_kernel<<<(N_EDGES + 255) / 256, 256>>>(edge_index);
    aggregate_kernel<<<(N_NODES * 32 + 255) / 256, 256>>>(x);
    transpose_kernel<<<K_TOT, HID_CH>>>(W_l, W_r);

    dim3 grid(N_TILES, 2);
    gemm_kernel<<<grid, 256, SMEM_BYTES>>>(b_l, out);
}

// round 8
// speedup vs baseline: 1.1894x; 1.1894x over previous
#include <cuda_runtime.h>
#include <cstdint>

#define N_NODES 50000
#define N_PAD   50048           // 782 * 64
#define N_EDGES 640000
#define IN_CH   128
#define HID_CH  256
#define K_TOT   256
#define TILE_M  64
#define TILE_N  128
#define M_TILES 782             // ceil(50000/64)
#define CHUNK_K 32
#define N_CHUNKS 8
#define PAD     36              // floats per smem row (conflict-free fragments)

// Scratch (__device__ globals zero-initialized; pad rows never written).
__device__ float g_agg[N_PAD * IN_CH];
__device__ float g_cnt[N_PAD];
__device__ float g_Bt[HID_CH * K_TOT];   // Bt[n][k] = Wcat[k][n], tf32-rounded

__device__ __forceinline__ uint32_t f2tf(float f) {
    uint32_t r;
    asm("cvt.rna.tf32.f32 %0, %1;" : "=r"(r) : "f"(f));
    return r;
}

// ---------------------------------------------------------------------------
// Kernel 1: zero accumulators (float4 stores).
// ---------------------------------------------------------------------------
__global__ void zero_kernel() {
    int idx = blockIdx.x * blockDim.x + threadIdx.x;
    int stride = gridDim.x * blockDim.x;
    const int total4 = (N_NODES * IN_CH) / 4;
    float4 z = make_float4(0.f, 0.f, 0.f, 0.f);
    for (int i = idx; i < total4; i += stride)
        reinterpret_cast<float4*>(g_agg)[i] = z;
    for (int i = idx; i < N_NODES; i += stride) g_cnt[i] = 0.0f;
}

// ---------------------------------------------------------------------------
// Kernel 2: per-edge scatter: red.global.add.v4.f32 (known 71us, L2 ceiling).
// ---------------------------------------------------------------------------
__global__ void scatter_kernel(const float* __restrict__ x,
                               const int* __restrict__ edge_index) {
    int warp = (blockIdx.x * blockDim.x + threadIdx.x) >> 5;
    int lane = threadIdx.x & 31;
    if (warp >= N_EDGES) return;

    int src = edge_index[warp];
    int dst = edge_index[N_EDGES + warp];

    float4 v = reinterpret_cast<const float4*>(x + (size_t)src * IN_CH)[lane];
    float* a = g_agg + (size_t)dst * IN_CH + lane * 4;
    asm volatile("red.global.add.v4.f32 [%0], {%1, %2, %3, %4};"
                 :: "l"(a), "f"(v.x), "f"(v.y), "f"(v.z), "f"(v.w) : "memory");
    if (lane == 0) atomicAdd(&g_cnt[dst], 1.0f);
}

// ---------------------------------------------------------------------------
// Kernel 3: transpose W into K-major Bt[n][k], tf32-rounded.
// ---------------------------------------------------------------------------
__global__ void transpose_kernel(const float* __restrict__ W_l,
                                 const float* __restrict__ W_r) {
    int k = blockIdx.x;
    int n = threadIdx.x;
    float v = (k < IN_CH) ? W_l[k * HID_CH + n] : W_r[(k - IN_CH) * HID_CH + n];
    g_Bt[n * K_TOT + k] = __uint_as_float(f2tf(v));
}

// ---------------------------------------------------------------------------
// Kernel 4: tf32 mma.sync GEMM, fused mean-prep (R5 structure), smaller tile.
// Block 64x128 tile, grid (782, 2). 8 warps = 2(M) x 4(N); warp tile 32x32.
// acc = 32 regs -> ~80 regs total -> 3 CTAs/SM (24 warps).
// ---------------------------------------------------------------------------
#define OFF_BIAS 0
#define OFF_A    512
#define A_STAGE  (TILE_M * PAD * 4)        // 9216
#define OFF_B    (OFF_A + 2 * A_STAGE)     // 18944
#define B_STAGE  (TILE_N * PAD * 4)        // 18432
#define SMEM_BYTES (OFF_B + 2 * B_STAGE)   // 55808

__device__ __forceinline__ void mma_tf32(float* c, const uint32_t* a,
                                         uint32_t b0, uint32_t b1) {
    asm("mma.sync.aligned.m16n8k8.row.col.f32.tf32.tf32.f32 "
        "{%0,%1,%2,%3}, {%4,%5,%6,%7}, {%8,%9}, {%0,%1,%2,%3};"
        : "+f"(c[0]), "+f"(c[1]), "+f"(c[2]), "+f"(c[3])
        : "r"(a[0]), "r"(a[1]), "r"(a[2]), "r"(a[3]), "r"(b0), "r"(b1));
}

__global__ void __launch_bounds__(256, 3)
gemm_kernel(const float* __restrict__ x,
            const float* __restrict__ b_l,
            float* __restrict__ out) {
    extern __shared__ char smem[];
    const int tid = threadIdx.x;
    const int wid = tid >> 5, lid = tid & 31;
    const int lrow = lid >> 2, lane4 = lid & 3;
    const int node0 = blockIdx.x * TILE_M;
    const int nblk0 = blockIdx.y * TILE_N;
    const int m_base = (wid & 1) * 32;
    const int n_base = (wid >> 1) * 32;

    float* bias_s = (float*)(smem + OFF_BIAS);
    if (tid < TILE_N) bias_s[tid] = b_l[nblk0 + tid];

    float4 aregs[2], bregs[4];
    int arow[2];

    // ---- chunk loader: LDG into registers (padded arrays -> no tail guard) ----
    auto load_chunk = [&](int c) {
        const int kc = c * CHUNK_K;
        #pragma unroll
        for (int t = 0; t < 2; ++t) {
            int idx = tid + t * 256;        // 512 float4 units for A
            int row = idx >> 3, j4 = idx & 7;
            int node = node0 + row;
            arow[t] = row * PAD + j4 * 4;
            float4 v;
            if (c < 4) {
                v = *reinterpret_cast<const float4*>(
                        g_agg + (size_t)node * IN_CH + kc + j4 * 4);
                float inv = 1.0f / fmaxf(g_cnt[node], 1.0f);
                v.x *= inv; v.y *= inv; v.z *= inv; v.w *= inv;
            } else if (node < N_NODES) {
                v = *reinterpret_cast<const float4*>(
                        x + (size_t)node * IN_CH + (kc - IN_CH) + j4 * 4);
            } else {
                v = make_float4(0.f, 0.f, 0.f, 0.f);
            }
            aregs[t] = v;
        }
        #pragma unroll
        for (int t = 0; t < 4; ++t) {       // 1024 float4 units for B
            int idx = tid + t * 256;
            int n = idx >> 3, j4 = idx & 7;
            bregs[t] = *reinterpret_cast<const float4*>(
                           g_Bt + (size_t)(nblk0 + n) * K_TOT + kc + j4 * 4);
        }
    };

    auto sts_chunk = [&](int buf) {
        float* As = (float*)(smem + OFF_A + buf * A_STAGE);
        float* Bs = (float*)(smem + OFF_B + buf * B_STAGE);
        #pragma unroll
        for (int t = 0; t < 2; ++t) {
            float4 v = aregs[t];
            float2 lo = make_float2(__uint_as_float(f2tf(v.x)), __uint_as_float(f2tf(v.y)));
            float2 hi = make_float2(__uint_as_float(f2tf(v.z)), __uint_as_float(f2tf(v.w)));
            *reinterpret_cast<float2*>(As + arow[t]) = lo;
            *reinterpret_cast<float2*>(As + arow[t] + 2) = hi;
        }
        #pragma unroll
        for (int t = 0; t < 4; ++t) {
            int idx = tid + t * 256;
            int n = idx >> 3, j4 = idx & 7;
            float4 v = bregs[t];            // already tf32
            *reinterpret_cast<float2*>(Bs + n * PAD + j4 * 4) = make_float2(v.x, v.y);
            *reinterpret_cast<float2*>(Bs + n * PAD + j4 * 4 + 2) = make_float2(v.z, v.w);
        }
    };

    float acc[2][4][4];
    #pragma unroll
    for (int mi = 0; mi < 2; ++mi)
        #pragma unroll
        for (int ni = 0; ni < 4; ++ni)
            #pragma unroll
            for (int j = 0; j < 4; ++j) acc[mi][ni][j] = 0.f;

    load_chunk(0);
    sts_chunk(0);
    __syncthreads();

    for (int c = 0; c < N_CHUNKS; ++c) {
        const int buf = c & 1;
        if (c < N_CHUNKS - 1) load_chunk(c + 1);   // LDGs in flight over compute

        const float* As = (const float*)(smem + OFF_A + buf * A_STAGE);
        const float* Bs = (const float*)(smem + OFF_B + buf * B_STAGE);
        #pragma unroll
        for (int ks = 0; ks < 4; ++ks) {
            const int k0 = ks * 8;
            uint32_t a[2][4];
            #pragma unroll
            for (int mi = 0; mi < 2; ++mi) {
                const float* ap = As + (m_base + mi * 16 + lrow) * PAD + k0 + lane4;
                a[mi][0] = __float_as_uint(ap[0]);
                a[mi][1] = __float_as_uint(ap[8 * PAD]);
                a[mi][2] = __float_as_uint(ap[4]);
                a[mi][3] = __float_as_uint(ap[8 * PAD + 4]);
            }
            #pragma unroll
            for (int ni = 0; ni < 4; ++ni) {
                const float* bp = Bs + (n_base + ni * 8 + lrow) * PAD + k0 + lane4;
                uint32_t b0 = __float_as_uint(bp[0]);
                uint32_t b1 = __float_as_uint(bp[4]);
                mma_tf32(acc[0][ni], a[0], b0, b1);
                mma_tf32(acc[1][ni], a[1], b0, b1);
            }
        }

        if (c < N_CHUNKS - 1) {
            sts_chunk(buf ^ 1);
            __syncthreads();
        }
    }

    // ---- epilogue: bias + store ----
    #pragma unroll
    for (int mi = 0; mi < 2; ++mi) {
        int row = node0 + m_base + mi * 16 + lrow;
        #pragma unroll
        for (int ni = 0; ni < 4; ++ni) {
            int col = n_base + ni * 8 + lane4 * 2;
            float b0 = bias_s[col], b1 = bias_s[col + 1];
            if (row < N_NODES) {
                *reinterpret_cast<float2*>(out + (size_t)row * HID_CH + nblk0 + col) =
                    make_float2(acc[mi][ni][0] + b0, acc[mi][ni][1] + b1);
            }
            if (row + 8 < N_NODES) {
                *reinterpret_cast<float2*>(out + (size_t)(row + 8) * HID_CH + nblk0 + col) =
                    make_float2(acc[mi][ni][2] + b0, acc[mi][ni][3] + b1);
            }
        }
    }
}

// ---------------------------------------------------------------------------
// Launch. Inputs: x f32[50000*128], edge_index i32[2*640000],
// W_l f32[128*256], b_l f32[256], W_r f32[128*256]. Out f32[50000*256].
// ---------------------------------------------------------------------------
extern "C" void kernel_launch(void* const* d_in, const int* in_sizes, int n_in,
                              void* d_out, int out_size) {
    const float* x = (const float*)d_in[0];
    const int* edge_index = (const int*)d_in[1];
    const float* W_l = (const float*)d_in[2];
    const float* b_l = (const float*)d_in[3];
    const float* W_r = (const float*)d_in[4];
    float* out = (float*)d_out;

    cudaFuncSetAttribute(gemm_kernel,
                         cudaFuncAttributeMaxDynamicSharedMemorySize, SMEM_BYTES);

    zero_kernel<<<592, 256>>>();
    scatter_kernel<<<(N_EDGES + 7) / 8, 256>>>(x, edge_index);
    transpose_kernel<<<K_TOT, HID_CH>>>(W_l, W_r);

    dim3 grid(M_TILES, 2);
    gemm_kernel<<<grid, 256, SMEM_BYTES>>>(x, b_l, out);
}

// round 9
// speedup vs baseline: 1.2577x; 1.0574x over previous
#include <cuda_runtime.h>
#include <cstdint>

#define N_NODES 50000
#define N_PAD   50048           // 391 * 128
#define N_EDGES 640000
#define IN_CH   128
#define HID_CH  256
#define K_TOT   256
#define TILE_M  128
#define TILE_N  128
#define N_TILES 391             // ceil(50000/128)
#define CHUNK_K 32
#define N_CHUNKS 8
#define PAD     36              // floats per smem row (16B-aligned, ldmatrix conflict-free)

// Scratch (__device__ globals zero-initialized; pad rows never written).
__device__ float g_agg[N_PAD * IN_CH];
__device__ float g_cnt[N_PAD];
__device__ float g_Bt[HID_CH * K_TOT];   // Bt[n][k] = Wcat[k][n], tf32-rounded

__device__ __forceinline__ uint32_t f2tf(float f) {
    uint32_t r;
    asm("cvt.rna.tf32.f32 %0, %1;" : "=r"(r) : "f"(f));
    return r;
}
__device__ __forceinline__ uint32_t smem_u32(const void* p) {
    return (uint32_t)__cvta_generic_to_shared(p);
}
__device__ __forceinline__ void ldsm_x4(uint32_t& r0, uint32_t& r1,
                                        uint32_t& r2, uint32_t& r3, uint32_t addr) {
    asm volatile("ldmatrix.sync.aligned.m8n8.x4.shared.b16 {%0,%1,%2,%3}, [%4];"
                 : "=r"(r0), "=r"(r1), "=r"(r2), "=r"(r3) : "r"(addr));
}

// ---------------------------------------------------------------------------
// Kernel 1: zero accumulators (float4 stores).
// ---------------------------------------------------------------------------
__global__ void zero_kernel() {
    int idx = blockIdx.x * blockDim.x + threadIdx.x;
    int stride = gridDim.x * blockDim.x;
    const int total4 = (N_NODES * IN_CH) / 4;
    float4 z = make_float4(0.f, 0.f, 0.f, 0.f);
    for (int i = idx; i < total4; i += stride)
        reinterpret_cast<float4*>(g_agg)[i] = z;
    for (int i = idx; i < N_NODES; i += stride) g_cnt[i] = 0.0f;
}

// ---------------------------------------------------------------------------
// Kernel 2: per-edge scatter: red.global.add.v4.f32 (known 71us, L2 ceiling).
// ---------------------------------------------------------------------------
__global__ void scatter_kernel(const float* __restrict__ x,
                               const int* __restrict__ edge_index) {
    int warp = (blockIdx.x * blockDim.x + threadIdx.x) >> 5;
    int lane = threadIdx.x & 31;
    if (warp >= N_EDGES) return;

    int src = edge_index[warp];
    int dst = edge_index[N_EDGES + warp];

    float4 v = reinterpret_cast<const float4*>(x + (size_t)src * IN_CH)[lane];
    float* a = g_agg + (size_t)dst * IN_CH + lane * 4;
    asm volatile("red.global.add.v4.f32 [%0], {%1, %2, %3, %4};"
                 :: "l"(a), "f"(v.x), "f"(v.y), "f"(v.z), "f"(v.w) : "memory");
    if (lane == 0) atomicAdd(&g_cnt[dst], 1.0f);
}

// ---------------------------------------------------------------------------
// Kernel 3: transpose W into K-major Bt[n][k], tf32-rounded.
// ---------------------------------------------------------------------------
__global__ void transpose_kernel(const float* __restrict__ W_l,
                                 const float* __restrict__ W_r) {
    int k = blockIdx.x;
    int n = threadIdx.x;
    float v = (k < IN_CH) ? W_l[k * HID_CH + n] : W_r[(k - IN_CH) * HID_CH + n];
    g_Bt[n * K_TOT + k] = __uint_as_float(f2tf(v));
}

// ---------------------------------------------------------------------------
// Kernel 4: tf32 mma.sync GEMM — R5 structure + ldmatrix fragment loads.
// Block 128x128, grid (391, 2). 8 warps = 4(M) x 2(N); warp tile 32x64.
// K=256 in 8 chunks of 32, double-buffered, register-staged LDG with fused mean.
// ---------------------------------------------------------------------------
#define OFF_BIAS 0
#define OFF_A    512
#define ABYTES   (TILE_M * PAD * 4)        // 18432
#define OFF_B    (OFF_A + 2 * ABYTES)      // 37376
#define SMEM_BYTES (OFF_B + 2 * ABYTES)    // 74240

__device__ __forceinline__ void mma_tf32(float* c, const uint32_t* a,
                                         uint32_t b0, uint32_t b1) {
    asm("mma.sync.aligned.m16n8k8.row.col.f32.tf32.tf32.f32 "
        "{%0,%1,%2,%3}, {%4,%5,%6,%7}, {%8,%9}, {%0,%1,%2,%3};"
        : "+f"(c[0]), "+f"(c[1]), "+f"(c[2]), "+f"(c[3])
        : "r"(a[0]), "r"(a[1]), "r"(a[2]), "r"(a[3]), "r"(b0), "r"(b1));
}

__global__ void __launch_bounds__(256, 2)
gemm_kernel(const float* __restrict__ x,
            const float* __restrict__ b_l,
            float* __restrict__ out) {
    extern __shared__ char smem[];
    const int tid = threadIdx.x;
    const int wid = tid >> 5, lid = tid & 31;
    const int lrow = lid >> 2, lane4 = lid & 3;
    const int node0 = blockIdx.x * TILE_M;
    const int nblk0 = blockIdx.y * TILE_N;
    const int m_base = (wid & 3) * 32;
    const int n_base = (wid >> 2) * 64;

    float* bias_s = (float*)(smem + OFF_BIAS);
    if (tid < TILE_N) bias_s[tid] = b_l[nblk0 + tid];

    // ldmatrix lane-address components.
    const int g = lid >> 3;          // matrix group 0..3
    const int rin = lid & 7;         // row within 8-row group
    // A x4 per mi: groups = (rows 0-7,k0) (rows 8-15,k0) (rows 0-7,k0+4) (rows 8-15,k0+4)
    uint32_t aoff[2];
    #pragma unroll
    for (int mi = 0; mi < 2; ++mi)
        aoff[mi] = ((m_base + mi * 16 + (g & 1) * 8 + rin) * PAD + (g >> 1) * 4) * 4;
    // B x4 per ni-pair p: groups = (n 0-7,k0) (n 0-7,k0+4) (n 8-15,k0) (n 8-15,k0+4)
    uint32_t boff[4];
    #pragma unroll
    for (int p = 0; p < 4; ++p)
        boff[p] = ((n_base + p * 16 + (g >> 1) * 8 + rin) * PAD + (g & 1) * 4) * 4;

    float4 aregs[4], bregs[4];
    int arow[4];

    // ---- chunk loader: LDG into registers (padded arrays -> agg path unguarded) ----
    auto load_chunk = [&](int c) {
        const int kc = c * CHUNK_K;
        #pragma unroll
        for (int t = 0; t < 4; ++t) {
            int idx = tid + t * 256;
            int row = idx >> 3, j4 = idx & 7;
            int node = node0 + row;
            arow[t] = row * PAD + j4 * 4;
            float4 v;
            if (c < 4) {
                v = *reinterpret_cast<const float4*>(
                        g_agg + (size_t)node * IN_CH + kc + j4 * 4);
                float inv = 1.0f / fmaxf(g_cnt[node], 1.0f);
                v.x *= inv; v.y *= inv; v.z *= inv; v.w *= inv;
            } else if (node < N_NODES) {
                v = *reinterpret_cast<const float4*>(
                        x + (size_t)node * IN_CH + (kc - IN_CH) + j4 * 4);
            } else {
                v = make_float4(0.f, 0.f, 0.f, 0.f);
            }
            aregs[t] = v;
        }
        #pragma unroll
        for (int t = 0; t < 4; ++t) {
            int idx = tid + t * 256;
            int n = idx >> 3, j4 = idx & 7;
            bregs[t] = *reinterpret_cast<const float4*>(
                           g_Bt + (size_t)(nblk0 + n) * K_TOT + kc + j4 * 4);
        }
    };

    auto sts_chunk = [&](int buf) {
        float* As = (float*)(smem + OFF_A + buf * ABYTES);
        float* Bs = (float*)(smem + OFF_B + buf * ABYTES);
        #pragma unroll
        for (int t = 0; t < 4; ++t) {
            float4 v = aregs[t];
            float2 lo = make_float2(__uint_as_float(f2tf(v.x)), __uint_as_float(f2tf(v.y)));
            float2 hi = make_float2(__uint_as_float(f2tf(v.z)), __uint_as_float(f2tf(v.w)));
            *reinterpret_cast<float2*>(As + arow[t]) = lo;
            *reinterpret_cast<float2*>(As + arow[t] + 2) = hi;
        }
        #pragma unroll
        for (int t = 0; t < 4; ++t) {
            int idx = tid + t * 256;
            int n = idx >> 3, j4 = idx & 7;
            float4 v = bregs[t];            // already tf32
            *reinterpret_cast<float2*>(Bs + n * PAD + j4 * 4) = make_float2(v.x, v.y);
            *reinterpret_cast<float2*>(Bs + n * PAD + j4 * 4 + 2) = make_float2(v.z, v.w);
        }
    };

    float acc[2][8][4];
    #pragma unroll
    for (int mi = 0; mi < 2; ++mi)
        #pragma unroll
        for (int ni = 0; ni < 8; ++ni)
            #pragma unroll
            for (int j = 0; j < 4; ++j) acc[mi][ni][j] = 0.f;

    load_chunk(0);
    sts_chunk(0);
    __syncthreads();

    for (int c = 0; c < N_CHUNKS; ++c) {
        const int buf = c & 1;
        if (c < N_CHUNKS - 1) load_chunk(c + 1);   // LDGs in flight over compute

        const uint32_t sAc = smem_u32(smem + OFF_A + buf * ABYTES);
        const uint32_t sBc = smem_u32(smem + OFF_B + buf * ABYTES);
        #pragma unroll
        for (int ks = 0; ks < 4; ++ks) {
            const uint32_t kb = ks * 32;   // 8 floats = 32 bytes
            uint32_t a[2][4];
            ldsm_x4(a[0][0], a[0][1], a[0][2], a[0][3], sAc + aoff[0] + kb);
            ldsm_x4(a[1][0], a[1][1], a[1][2], a[1][3], sAc + aoff[1] + kb);
            #pragma unroll
            for (int p = 0; p < 4; ++p) {
                uint32_t b0, b1, b2, b3;
                ldsm_x4(b0, b1, b2, b3, sBc + boff[p] + kb);
                mma_tf32(acc[0][2 * p],     a[0], b0, b1);
                mma_tf32(acc[1][2 * p],     a[1], b0, b1);
                mma_tf32(acc[0][2 * p + 1], a[0], b2, b3);
                mma_tf32(acc[1][2 * p + 1], a[1], b2, b3);
            }
        }

        if (c < N_CHUNKS - 1) {
            sts_chunk(buf ^ 1);
            __syncthreads();
        }
    }

    // ---- epilogue: bias + store ----
    #pragma unroll
    for (int mi = 0; mi < 2; ++mi) {
        int row = node0 + m_base + mi * 16 + lrow;
        #pragma unroll
        for (int ni = 0; ni < 8; ++ni) {
            int col = n_base + ni * 8 + lane4 * 2;
            float b0 = bias_s[col], b1 = bias_s[col + 1];
            if (row < N_NODES) {
                *reinterpret_cast<float2*>(out + (size_t)row * HID_CH + nblk0 + col) =
                    make_float2(acc[mi][ni][0] + b0, acc[mi][ni][1] + b1);
            }
            if (row + 8 < N_NODES) {
                *reinterpret_cast<float2*>(out + (size_t)(row + 8) * HID_CH + nblk0 + col) =
                    make_float2(acc[mi][ni][2] + b0, acc[mi][ni][3] + b1);
            }
        }
    }
}

// ---------------------------------------------------------------------------
// Launch. Inputs: x f32[50000*128], edge_index i32[2*640000],
// W_l f32[128*256], b_l f32[256], W_r f32[128*256]. Out f32[50000*256].
// ---------------------------------------------------------------------------
extern "C" void kernel_launch(void* const* d_in, const int* in_sizes, int n_in,
                              void* d_out, int out_size) {
    const float* x = (const float*)d_in[0];
    const int* edge_index = (const int*)d_in[1];
    const float* W_l = (const float*)d_in[2];
    const float* b_l = (const float*)d_in[3];
    const float* W_r = (const float*)d_in[4];
    float* out = (float*)d_out;

    cudaFuncSetAttribute(gemm_kernel,
                         cudaFuncAttributeMaxDynamicSharedMemorySize, SMEM_BYTES);

    zero_kernel<<<592, 256>>>();
    scatter_kernel<<<(N_EDGES + 7) / 8, 256>>>(x, edge_index);
    transpose_kernel<<<K_TOT, HID_CH>>>(W_l, W_r);

    dim3 grid(N_TILES, 2);
    gemm_kernel<<<grid, 256, SMEM_BYTES>>>(x, b_l, out);
}